// round 14
// baseline (speedup 1.0000x reference)
#include <cuda_runtime.h>
#include <cuda_fp16.h>
#include <math.h>
#include <stdint.h>

#define NB 16
#define NC 256
#define NH 64
#define NW 64
#define NTAP 9
#define SEXP (NC*NC*NTAP)
#define QP 66
#define QN (QP*QP)                  /* 4356 padded pixels */
#define TILE_M 128
#define TILE_N 192
#define KC 32
#define NCHUNK 8
#define NTHREADS 384
#define A_TAP_BYTES 8192            /* 128 rows x 32 ch fp16, fragment-major */
#define A_CHUNK_BYTES (NTAP*A_TAP_BYTES)   /* 73728 */
#define B_PITCH 64                  /* 64B data; conflict-free for uint4 loads */
#define B_ROWS 328                  /* 192 + 2*67 = 326, padded */
#define B_BYTES (B_ROWS*B_PITCH)    /* 20992 */
#define SMEM_TOTAL (2*A_CHUNK_BYTES + 2*B_BYTES)  /* 189440 */
#define QTILES 23                   /* 23*192 = 4416 >= 4356 */
#define FOLD_BLOCKS (SEXP/256)      /* 2304 */
#define XPAD_BLOCKS (4*QP*NB)       /* 4224 */

__device__ float g_pooled[NB*NC];
__device__ float g_routing[NB*4];
// A fp16 fragment-major: [b][otile(2)][chunk(8)][t(9)][inner 4096]
__device__ __align__(1024) __half g_weff[(size_t)NB*NTAP*NC*NC];
// B fp16: [b][q][c_perm], perm within 32-group: pos32 = tig*8 + kk*4 + khi*2 + e
__device__ __align__(1024) __half g_xpad[(size_t)NB*QN*NC];

// ------------------------------------------------------------------ helpers
__device__ __forceinline__ uint32_t s2u(const void* p){
    uint32_t a;
    asm("{ .reg .u64 t; cvta.to.shared.u64 t, %1; cvt.u32.u64 %0, t; }" : "=r"(a) : "l"(p));
    return a;
}
__device__ __forceinline__ void cp16(uint32_t dst, const void* src, int szbytes){
    asm volatile("cp.async.cg.shared.global [%0], [%1], 16, %2;"
                 :: "r"(dst), "l"(src), "r"(szbytes) : "memory");
}
__device__ __forceinline__ void cp_commit(){
    asm volatile("cp.async.commit_group;" ::: "memory");
}
template<int N> __device__ __forceinline__ void cp_wait(){
    asm volatile("cp.async.wait_group %0;" :: "n"(N) : "memory");
}
__device__ __forceinline__ void mma16(float* d, const uint4 a, const uint32_t b0,
                                      const uint32_t b1){
    asm volatile("mma.sync.aligned.m16n8k16.row.col.f32.f16.f16.f32 "
        "{%0,%1,%2,%3}, {%4,%5,%6,%7}, {%8,%9}, {%0,%1,%2,%3};"
        : "+f"(d[0]), "+f"(d[1]), "+f"(d[2]), "+f"(d[3])
        : "r"(a.x), "r"(a.y), "r"(a.z), "r"(a.w), "r"(b0), "r"(b1));
}

// ------------------------------------------------------------------ prep
__global__ void pool_kernel(const float* __restrict__ x) {
    int bc = blockIdx.x;
    const float4* p = (const float4*)(x + (size_t)bc * NH * NW);
    float s = 0.f;
    for (int i = threadIdx.x; i < NH*NW/4; i += blockDim.x) {
        float4 v = p[i];
        s += v.x + v.y + v.z + v.w;
    }
    #pragma unroll
    for (int o = 16; o; o >>= 1) s += __shfl_xor_sync(0xffffffffu, s, o);
    __shared__ float red[4];
    if ((threadIdx.x & 31) == 0) red[threadIdx.x >> 5] = s;
    __syncthreads();
    if (threadIdx.x == 0)
        g_pooled[bc] = (red[0]+red[1]+red[2]+red[3]) * (1.0f/(NH*NW));
}

__global__ void route_kernel(const float* __restrict__ wr, const float* __restrict__ br) {
    int t = threadIdx.x;
    if (t >= NB*4) return;
    int b = t >> 2, e = t & 3;
    float acc = br[e];
    const float* pw = wr + e*NC;
    const float* pp = g_pooled + b*NC;
    #pragma unroll 8
    for (int c = 0; c < NC; ++c) acc = fmaf(pp[c], pw[c], acc);
    g_routing[t] = 1.f/(1.f + __expf(-acc));
}

// Fused fold + xpad (4 total launches so ncu lands on conv).
__global__ void prep_kernel(const float* __restrict__ we,
                            const float* __restrict__ x) {
    __shared__ float s[64*65];
    if (blockIdx.x < FOLD_BLOCKS) {
        int lin = blockIdx.x * 256 + threadIdx.x;   // 0 .. 589823
        int inner = lin & 4095;
        int rest  = lin >> 12;
        int t     = rest % 9;
        int oc    = rest / 9;
        int chunk = oc & 7;
        int otile = oc >> 3;
        int e    = inner & 1;
        int reg  = (inner >> 1) & 3;
        int lane = (inner >> 3) & 31;
        int mblk = (inner >> 8) & 7;
        int kk   = inner >> 11;
        int tig = lane & 3, g8 = lane >> 2;
        int khi = reg >> 1, ohi = reg & 1;
        int o = otile*128 + mblk*16 + ohi*8 + g8;
        int c = chunk*32 + kk*16 + khi*8 + tig*2 + e;

        size_t wi = ((size_t)o*NC + c)*NTAP + t;
        float w0 = we[wi], w1 = we[wi + (size_t)SEXP];
        float w2 = we[wi + 2*(size_t)SEXP], w3 = we[wi + 3*(size_t)SEXP];
        #pragma unroll
        for (int b = 0; b < NB; ++b) {
            const float* r = g_routing + b*4;
            g_weff[(size_t)b*(NTAP*NC*NC) + lin] =
                __float2half_rn(w0*r[0] + w1*r[1] + w2*r[2] + w3*r[3]);
        }
    } else {
        int blk = blockIdx.x - FOLD_BLOCKS;
        int c0 = (blk & 3) * 64;
        int hp = (blk >> 2) % QP;
        int b  = blk / (4*QP);
        int h = hp - 1;
        bool hv = (h >= 0 && h < NH);
        if (hv) {
            const float* xp = x + ((size_t)(b*NC + c0))*(NH*NW) + (size_t)h*NW;
            for (int j = 0; j < 16; ++j) {
                int idx = j*256 + threadIdx.x;
                int i = idx >> 6, w = idx & 63;
                s[w*65 + i] = xp[(size_t)i*(NH*NW) + w];
            }
        }
        __syncthreads();
        __half* op = g_xpad + ((size_t)b*QN + (size_t)hp*QP)*NC + c0;
        for (int j = 0; j < 17; ++j) {
            int idx = j*256 + threadIdx.x;
            if (idx >= QP*64) break;
            int i = idx & 63, wp = idx >> 6;
            float v = 0.f;
            if (hv && wp >= 1 && wp <= 64) v = s[(wp-1)*65 + i];
            int c32 = i & 31;
            int kk = (c32 >> 4) & 1, khi = (c32 >> 3) & 1;
            int tg = (c32 >> 1) & 3, e = c32 & 1;
            int ipos = (i & ~31) | (tg*8 + kk*4 + khi*2 + e);
            op[(size_t)wp*NC + ipos] = __float2half_rn(v);
        }
    }
}

// ------------------------------------------------------------------ conv GEMM
// smem: [A buf0 72KB][A buf1 72KB][B buf0 20.5KB][B buf1 20.5KB]
__device__ __forceinline__ void load_chunk(uint32_t sb, int chunk, int q0,
                                           const __half* aGbase, const __half* bG,
                                           int tid)
{
    int bufsel = chunk & 1;
    const __half* aG = aGbase + (size_t)chunk*(NTAP*4096);
    uint32_t aDst = sb + bufsel*A_CHUNK_BYTES;
    #pragma unroll
    for (int j = 0; j < 12; ++j) {
        int seg = tid + j*NTHREADS;
        cp16(aDst + seg*16, aG + (size_t)seg*8, 16);
    }
    const __half* bC = bG + chunk*KC;
    uint32_t bDst = sb + 2*A_CHUNK_BYTES + bufsel*B_BYTES;
    #pragma unroll
    for (int jj = 0; jj < 4; ++jj) {
        int seg = tid + jj*NTHREADS;
        if (seg < 326*4) {
            int row = seg >> 2, j = seg & 3;
            int q = q0 - 67 + row;
            bool v = ((unsigned)q < (unsigned)QN);
            const __half* src = bC + (size_t)(v ? q : 0)*NC + j*8;
            cp16(bDst + row*B_PITCH + j*16, src, v ? 16 : 0);
        }
    }
}

__global__ void __launch_bounds__(NTHREADS, 1)
conv_mma_kernel(const float* __restrict__ gamma, const float* __restrict__ beta,
                const float* __restrict__ mean,  const float* __restrict__ var,
                float* __restrict__ out)
{
    extern __shared__ __align__(128) char smem[];
    const uint32_t sb = s2u(smem);
    const int tid = threadIdx.x, wid = tid >> 5, lid = tid & 31;
    // warp grid: 4 (M) x 3 (N). SMSP id = wid & 3 = wmM, so warps sharing an
    // SMSP differ in wnN -> tap rotation below staggers SMSP-mates.
    const int wmM = wid & 3;
    const int wnN = wid >> 2;
    const int g = lid >> 2, tig = lid & 3;
    const int b  = blockIdx.z;
    const int otile = blockIdx.y;
    const int o0 = otile * TILE_M;
    const int q0 = blockIdx.x * TILE_N;
    const int trot = wnN * 3;          // per-warp tap phase

    const __half* bG = g_xpad + (size_t)b*QN*NC;
    const __half* aGbase = g_weff + (size_t)b*(NTAP*NC*NC)
                         + (size_t)otile*(8*NTAP*4096);

    float acc[2][8][4];
    #pragma unroll
    for (int mi = 0; mi < 2; ++mi)
        #pragma unroll
        for (int ni = 0; ni < 8; ++ni)
            #pragma unroll
            for (int k = 0; k < 4; ++k) acc[mi][ni][k] = 0.f;

    load_chunk(sb, 0, q0, aGbase, bG, tid);
    cp_commit();

    uint4 Br[2][8];

    #pragma unroll 1
    for (int chunk = 0; chunk < NCHUNK; ++chunk) {
        __syncthreads();
        if (chunk + 1 < NCHUNK)
            load_chunk(sb, chunk + 1, q0, aGbase, bG, tid);
        cp_commit();
        cp_wait<1>();
        __syncthreads();

        const char* aBuf = smem + (chunk & 1)*A_CHUNK_BYTES;
        const char* bBase = smem + 2*A_CHUNK_BYTES + (chunk & 1)*B_BYTES;
        const char* bLane = bBase + (wnN*64 + g + 67)*B_PITCH + tig*16;

        int tt = trot;                       // this warp's first tap
        // preload B fragments for tap tt
        {
            int dh = tt / 3, dw = tt - dh*3;
            const char* bW = bLane + ((dh-1)*QP + (dw-1))*B_PITCH;
            #pragma unroll
            for (int ni = 0; ni < 8; ++ni)
                Br[0][ni] = *(const uint4*)(bW + ni*8*B_PITCH);
        }

        #pragma unroll
        for (int t = 0; t < NTAP; ++t) {
            const char* aT = aBuf + tt*A_TAP_BYTES;
            // prefetch next tap's B into the other bank
            int ttn = (tt == 8) ? 0 : tt + 1;
            if (t + 1 < NTAP) {
                int dh2 = ttn / 3, dw2 = ttn - dh2*3;
                const char* bW = bLane + ((dh2-1)*QP + (dw2-1))*B_PITCH;
                #pragma unroll
                for (int ni = 0; ni < 8; ++ni)
                    Br[(t+1) & 1][ni] = *(const uint4*)(bW + ni*8*B_PITCH);
            }
            const uint4* cur = Br[t & 1];
            #pragma unroll
            for (int kk = 0; kk < 2; ++kk) {
                uint4 a[2];
                #pragma unroll
                for (int mi = 0; mi < 2; ++mi)
                    a[mi] = *(const uint4*)(aT + ((kk*8 + wmM*2 + mi)*32 + lid)*16);
                #pragma unroll
                for (int mi = 0; mi < 2; ++mi)
                    #pragma unroll
                    for (int ni = 0; ni < 8; ++ni) {
                        uint32_t b0 = kk ? cur[ni].z : cur[ni].x;
                        uint32_t b1 = kk ? cur[ni].w : cur[ni].y;
                        mma16(acc[mi][ni], a[mi], b0, b1);
                    }
            }
            tt = ttn;
        }
    }

    // ---------------- epilogue: BN + SiLU + guarded stores
    float inv[2][2], add[2][2];
    #pragma unroll
    for (int mi = 0; mi < 2; ++mi)
        #pragma unroll
        for (int hi = 0; hi < 2; ++hi) {
            int o = o0 + wmM*32 + mi*16 + g + hi*8;
            float iv = gamma[o] * rsqrtf(var[o] + 1e-5f);
            inv[mi][hi] = iv;
            add[mi][hi] = beta[o] - mean[o] * iv;
        }
    #pragma unroll
    for (int mi = 0; mi < 2; ++mi) {
        #pragma unroll
        for (int ni = 0; ni < 8; ++ni) {
            #pragma unroll
            for (int k = 0; k < 4; ++k) {
                int hi = k >> 1, c = k & 1;
                int q = q0 + wnN*64 + ni*8 + 2*tig + c;
                int hp = q / QP, wp = q - hp*QP;
                if (q < QN && hp >= 1 && hp <= NH && wp >= 1 && wp <= NW) {
                    int o = o0 + wmM*32 + mi*16 + g + hi*8;
                    float z = acc[mi][ni][k] * inv[mi][hi] + add[mi][hi];
                    out[(((size_t)b*NC + o)*NH + hp - 1)*NW + wp - 1] =
                        z / (1.f + __expf(-z));
                }
            }
        }
    }
}

// ------------------------------------------------------------------ launch
extern "C" void kernel_launch(void* const* d_in, const int* in_sizes, int n_in,
                              void* d_out, int out_size) {
    const float* x        = (const float*)d_in[0];
    const float* w_route  = (const float*)d_in[1];
    const float* b_route  = (const float*)d_in[2];
    const float* w_expert = (const float*)d_in[3];
    const float* bn_gamma = (const float*)d_in[4];
    const float* bn_beta  = (const float*)d_in[5];
    const float* bn_mean  = (const float*)d_in[6];
    const float* bn_var   = (const float*)d_in[7];
    float* out = (float*)d_out;

    cudaFuncSetAttribute(conv_mma_kernel,
                         cudaFuncAttributeMaxDynamicSharedMemorySize, SMEM_TOTAL);

    pool_kernel<<<NB*NC, 128>>>(x);
    route_kernel<<<1, 64>>>(w_route, b_route);
    prep_kernel<<<FOLD_BLOCKS + XPAD_BLOCKS, 256>>>(w_expert, x);
    dim3 grid(QTILES, NC/TILE_M, NB);
    conv_mma_kernel<<<grid, NTHREADS, SMEM_TOTAL>>>(bn_gamma, bn_beta, bn_mean, bn_var, out);
}

// round 15
// speedup vs baseline: 1.5137x; 1.5137x over previous
#include <cuda_runtime.h>
#include <cuda_fp16.h>
#include <math.h>
#include <stdint.h>

#define NB 16
#define NC 256
#define NH 64
#define NW 64
#define NTAP 9
#define SEXP (NC*NC*NTAP)
#define QP 66
#define QN (QP*QP)                  /* 4356 padded pixels */
#define TILE_M 128
#define TILE_N 192
#define KC 32
#define NCHUNK 8
#define NTHREADS 384
#define A_TAP_BYTES 8192            /* 128 rows x 32 ch fp16, fragment-major */
#define A_CHUNK_BYTES (NTAP*A_TAP_BYTES)   /* 73728 */
#define B_PITCH 64                  /* 64B data; conflict-free for uint4 loads */
#define B_ROWS 328                  /* 192 + 2*67 = 326, padded */
#define B_BYTES (B_ROWS*B_PITCH)    /* 20992 */
#define SMEM_TOTAL (2*A_CHUNK_BYTES + 2*B_BYTES)  /* 189440 */
#define QTILES 23                   /* 23*192 = 4416 >= 4356 */
#define NTILES (NB*2*QTILES)        /* 736 */
#define GRIDX 148                   /* persistent: 1 CTA per SM */
#define FOLD_BLOCKS (SEXP/256)      /* 2304 */
#define XPAD_BLOCKS (4*QP*NB)       /* 4224 */

__device__ float g_pooled[NB*NC];
__device__ float g_routing[NB*4];
// A fp16 fragment-major: [b][otile(2)][chunk(8)][t(9)][inner 4096]
__device__ __align__(1024) __half g_weff[(size_t)NB*NTAP*NC*NC];
// B fp16: [b][q][c_perm], perm within 32-group: pos32 = tig*8 + kk*4 + khi*2 + e
__device__ __align__(1024) __half g_xpad[(size_t)NB*QN*NC];

// ------------------------------------------------------------------ helpers
__device__ __forceinline__ uint32_t s2u(const void* p){
    uint32_t a;
    asm("{ .reg .u64 t; cvta.to.shared.u64 t, %1; cvt.u32.u64 %0, t; }" : "=r"(a) : "l"(p));
    return a;
}
__device__ __forceinline__ void cp16(uint32_t dst, const void* src, int szbytes){
    asm volatile("cp.async.cg.shared.global [%0], [%1], 16, %2;"
                 :: "r"(dst), "l"(src), "r"(szbytes) : "memory");
}
__device__ __forceinline__ void cp_commit(){
    asm volatile("cp.async.commit_group;" ::: "memory");
}
template<int N> __device__ __forceinline__ void cp_wait(){
    asm volatile("cp.async.wait_group %0;" :: "n"(N) : "memory");
}
__device__ __forceinline__ void mma16(float* d, const uint4 a, const uint32_t b0,
                                      const uint32_t b1){
    asm volatile("mma.sync.aligned.m16n8k16.row.col.f32.f16.f16.f32 "
        "{%0,%1,%2,%3}, {%4,%5,%6,%7}, {%8,%9}, {%0,%1,%2,%3};"
        : "+f"(d[0]), "+f"(d[1]), "+f"(d[2]), "+f"(d[3])
        : "r"(a.x), "r"(a.y), "r"(a.z), "r"(a.w), "r"(b0), "r"(b1));
}

// ------------------------------------------------------------------ prep
__global__ void pool_kernel(const float* __restrict__ x) {
    int bc = blockIdx.x;
    const float4* p = (const float4*)(x + (size_t)bc * NH * NW);
    float s = 0.f;
    for (int i = threadIdx.x; i < NH*NW/4; i += blockDim.x) {
        float4 v = p[i];
        s += v.x + v.y + v.z + v.w;
    }
    #pragma unroll
    for (int o = 16; o; o >>= 1) s += __shfl_xor_sync(0xffffffffu, s, o);
    __shared__ float red[4];
    if ((threadIdx.x & 31) == 0) red[threadIdx.x >> 5] = s;
    __syncthreads();
    if (threadIdx.x == 0)
        g_pooled[bc] = (red[0]+red[1]+red[2]+red[3]) * (1.0f/(NH*NW));
}

__global__ void route_kernel(const float* __restrict__ wr, const float* __restrict__ br) {
    int t = threadIdx.x;
    if (t >= NB*4) return;
    int b = t >> 2, e = t & 3;
    float acc = br[e];
    const float* pw = wr + e*NC;
    const float* pp = g_pooled + b*NC;
    #pragma unroll 8
    for (int c = 0; c < NC; ++c) acc = fmaf(pp[c], pw[c], acc);
    g_routing[t] = 1.f/(1.f + __expf(-acc));
}

// Fused fold + xpad (4 total launches so ncu lands on conv).
__global__ void prep_kernel(const float* __restrict__ we,
                            const float* __restrict__ x) {
    __shared__ float s[64*65];
    if (blockIdx.x < FOLD_BLOCKS) {
        int lin = blockIdx.x * 256 + threadIdx.x;   // 0 .. 589823
        int inner = lin & 4095;
        int rest  = lin >> 12;
        int t     = rest % 9;
        int oc    = rest / 9;
        int chunk = oc & 7;
        int otile = oc >> 3;
        int e    = inner & 1;
        int reg  = (inner >> 1) & 3;
        int lane = (inner >> 3) & 31;
        int mblk = (inner >> 8) & 7;
        int kk   = inner >> 11;
        int tig = lane & 3, g8 = lane >> 2;
        int khi = reg >> 1, ohi = reg & 1;
        int o = otile*128 + mblk*16 + ohi*8 + g8;
        int c = chunk*32 + kk*16 + khi*8 + tig*2 + e;

        size_t wi = ((size_t)o*NC + c)*NTAP + t;
        float w0 = we[wi], w1 = we[wi + (size_t)SEXP];
        float w2 = we[wi + 2*(size_t)SEXP], w3 = we[wi + 3*(size_t)SEXP];
        #pragma unroll
        for (int b = 0; b < NB; ++b) {
            const float* r = g_routing + b*4;
            g_weff[(size_t)b*(NTAP*NC*NC) + lin] =
                __float2half_rn(w0*r[0] + w1*r[1] + w2*r[2] + w3*r[3]);
        }
    } else {
        int blk = blockIdx.x - FOLD_BLOCKS;
        int c0 = (blk & 3) * 64;
        int hp = (blk >> 2) % QP;
        int b  = blk / (4*QP);
        int h = hp - 1;
        bool hv = (h >= 0 && h < NH);
        if (hv) {
            const float* xp = x + ((size_t)(b*NC + c0))*(NH*NW) + (size_t)h*NW;
            for (int j = 0; j < 16; ++j) {
                int idx = j*256 + threadIdx.x;
                int i = idx >> 6, w = idx & 63;
                s[w*65 + i] = xp[(size_t)i*(NH*NW) + w];
            }
        }
        __syncthreads();
        __half* op = g_xpad + ((size_t)b*QN + (size_t)hp*QP)*NC + c0;
        for (int j = 0; j < 17; ++j) {
            int idx = j*256 + threadIdx.x;
            if (idx >= QP*64) break;
            int i = idx & 63, wp = idx >> 6;
            float v = 0.f;
            if (hv && wp >= 1 && wp <= 64) v = s[(wp-1)*65 + i];
            int c32 = i & 31;
            int kk = (c32 >> 4) & 1, khi = (c32 >> 3) & 1;
            int tg = (c32 >> 1) & 3, e = c32 & 1;
            int ipos = (i & ~31) | (tg*8 + kk*4 + khi*2 + e);
            op[(size_t)wp*NC + ipos] = __float2half_rn(v);
        }
    }
}

// ------------------------------------------------------------------ conv GEMM
// smem: [A buf0 72KB][A buf1 72KB][B buf0 20.5KB][B buf1 20.5KB]
__device__ __forceinline__ void decode_tile(int tau, int& b, int& otile, int& q0){
    b = tau / (2*QTILES);
    int r = tau - b*(2*QTILES);
    otile = r / QTILES;
    q0 = (r - otile*QTILES) * TILE_N;
}

__device__ __forceinline__ void load_chunk(uint32_t sb, int bufsel, int chunk,
                                           int b, int otile, int q0, int tid)
{
    const __half* aG = g_weff + (size_t)b*(NTAP*NC*NC)
                     + (size_t)otile*(8*NTAP*4096) + (size_t)chunk*(NTAP*4096);
    uint32_t aDst = sb + bufsel*A_CHUNK_BYTES;
    #pragma unroll
    for (int j = 0; j < 12; ++j) {
        int seg = tid + j*NTHREADS;
        cp16(aDst + seg*16, aG + (size_t)seg*8, 16);
    }
    const __half* bC = g_xpad + (size_t)b*QN*NC + chunk*KC;
    uint32_t bDst = sb + 2*A_CHUNK_BYTES + bufsel*B_BYTES;
    #pragma unroll
    for (int jj = 0; jj < 4; ++jj) {
        int seg = tid + jj*NTHREADS;
        if (seg < 326*4) {
            int row = seg >> 2, j = seg & 3;
            int q = q0 - 67 + row;
            bool v = ((unsigned)q < (unsigned)QN);
            const __half* src = bC + (size_t)(v ? q : 0)*NC + j*8;
            cp16(bDst + row*B_PITCH + j*16, src, v ? 16 : 0);
        }
    }
}

__global__ void __launch_bounds__(NTHREADS, 1)
conv_mma_kernel(const float* __restrict__ gamma, const float* __restrict__ beta,
                const float* __restrict__ mean,  const float* __restrict__ var,
                float* __restrict__ out)
{
    extern __shared__ __align__(128) char smem[];
    const uint32_t sb = s2u(smem);
    const int tid = threadIdx.x, wid = tid >> 5, lid = tid & 31;
    const int wmM = wid & 3;          // 4 warps over M
    const int wnN = wid >> 2;         // 3 warps over N
    const int g = lid >> 2, tig = lid & 3;

    int tau = blockIdx.x;
    if (tau >= NTILES) return;
    int cb, cot, cq0;
    decode_tile(tau, cb, cot, cq0);
    int nb = cb, not2 = cot, nq0 = cq0;

    float acc[2][8][4];
    #pragma unroll
    for (int mi = 0; mi < 2; ++mi)
        #pragma unroll
        for (int ni = 0; ni < 8; ++ni)
            #pragma unroll
            for (int k = 0; k < 4; ++k) acc[mi][ni][k] = 0.f;

    // prologue: (tile0, chunk0) -> buffer 0
    load_chunk(sb, 0, 0, cb, cot, cq0, tid);
    cp_commit();
    int cnt = 0;
    uint4 Br[2][8];

    #pragma unroll 1
    while (tau < NTILES) {
        #pragma unroll 1
        for (int chunk = 0; chunk < NCHUNK; ++chunk) {
            __syncthreads();
            if (chunk + 1 < NCHUNK) {
                load_chunk(sb, (cnt+1) & 1, chunk + 1, cb, cot, cq0, tid);
            } else if (tau + GRIDX < NTILES) {
                decode_tile(tau + GRIDX, nb, not2, nq0);
                load_chunk(sb, (cnt+1) & 1, 0, nb, not2, nq0, tid);
            }
            cp_commit();
            cp_wait<1>();
            __syncthreads();

            const char* aBuf = smem + (cnt & 1)*A_CHUNK_BYTES;
            const char* bBase = smem + 2*A_CHUNK_BYTES + (cnt & 1)*B_BYTES;
            const char* bLane = bBase + (wnN*64 + g + 67)*B_PITCH + tig*16;

            // preload tap 0 B fragments (shift -67)
            {
                const char* bW = bLane + (-67)*B_PITCH;
                #pragma unroll
                for (int ni = 0; ni < 8; ++ni)
                    Br[0][ni] = *(const uint4*)(bW + ni*8*B_PITCH);
            }
            #pragma unroll
            for (int t = 0; t < NTAP; ++t) {
                const char* aT = aBuf + t*A_TAP_BYTES;
                if (t + 1 < NTAP) {
                    const int dh2 = (t+1) / 3, dw2 = (t+1) - dh2*3;
                    const char* bW = bLane + ((dh2-1)*QP + (dw2-1))*B_PITCH;
                    #pragma unroll
                    for (int ni = 0; ni < 8; ++ni)
                        Br[(t+1) & 1][ni] = *(const uint4*)(bW + ni*8*B_PITCH);
                }
                const uint4* cur = Br[t & 1];
                #pragma unroll
                for (int kk = 0; kk < 2; ++kk) {
                    uint4 a[2];
                    #pragma unroll
                    for (int mi = 0; mi < 2; ++mi)
                        a[mi] = *(const uint4*)(aT + ((kk*8 + wmM*2 + mi)*32 + lid)*16);
                    #pragma unroll
                    for (int mi = 0; mi < 2; ++mi)
                        #pragma unroll
                        for (int ni = 0; ni < 8; ++ni) {
                            uint32_t b0 = kk ? cur[ni].z : cur[ni].x;
                            uint32_t b1 = kk ? cur[ni].w : cur[ni].y;
                            mma16(acc[mi][ni], a[mi], b0, b1);
                        }
                }
            }
            cnt++;
        }

        // ---------------- epilogue (next tile's chunk0 already in flight)
        {
            const int o0 = cot * TILE_M;
            float inv[2][2], add[2][2];
            #pragma unroll
            for (int mi = 0; mi < 2; ++mi)
                #pragma unroll
                for (int hi = 0; hi < 2; ++hi) {
                    int o = o0 + wmM*32 + mi*16 + g + hi*8;
                    float iv = gamma[o] * rsqrtf(var[o] + 1e-5f);
                    inv[mi][hi] = iv;
                    add[mi][hi] = beta[o] - mean[o] * iv;
                }
            #pragma unroll
            for (int mi = 0; mi < 2; ++mi) {
                #pragma unroll
                for (int ni = 0; ni < 8; ++ni) {
                    #pragma unroll
                    for (int k = 0; k < 4; ++k) {
                        int hi = k >> 1, c = k & 1;
                        int q = cq0 + wnN*64 + ni*8 + 2*tig + c;
                        int hp = q / QP, wp = q - hp*QP;
                        if (q < QN && hp >= 1 && hp <= NH && wp >= 1 && wp <= NW) {
                            int o = o0 + wmM*32 + mi*16 + g + hi*8;
                            float z = acc[mi][ni][k] * inv[mi][hi] + add[mi][hi];
                            out[(((size_t)cb*NC + o)*NH + hp - 1)*NW + wp - 1] =
                                z / (1.f + __expf(-z));
                        }
                        acc[mi][ni][k] = 0.f;
                    }
                }
            }
        }
        tau += GRIDX;
        cb = nb; cot = not2; cq0 = nq0;
    }
}

// ------------------------------------------------------------------ launch
extern "C" void kernel_launch(void* const* d_in, const int* in_sizes, int n_in,
                              void* d_out, int out_size) {
    const float* x        = (const float*)d_in[0];
    const float* w_route  = (const float*)d_in[1];
    const float* b_route  = (const float*)d_in[2];
    const float* w_expert = (const float*)d_in[3];
    const float* bn_gamma = (const float*)d_in[4];
    const float* bn_beta  = (const float*)d_in[5];
    const float* bn_mean  = (const float*)d_in[6];
    const float* bn_var   = (const float*)d_in[7];
    float* out = (float*)d_out;

    cudaFuncSetAttribute(conv_mma_kernel,
                         cudaFuncAttributeMaxDynamicSharedMemorySize, SMEM_TOTAL);

    pool_kernel<<<NB*NC, 128>>>(x);
    route_kernel<<<1, 64>>>(w_route, b_route);
    prep_kernel<<<FOLD_BLOCKS + XPAD_BLOCKS, 256>>>(w_expert, x);
    conv_mma_kernel<<<GRIDX, NTHREADS, SMEM_TOTAL>>>(bn_gamma, bn_beta, bn_mean, bn_var, out);
}

// round 16
// speedup vs baseline: 1.5605x; 1.0309x over previous
#include <cuda_runtime.h>
#include <cuda_fp16.h>
#include <math.h>
#include <stdint.h>

#define NB 16
#define NC 256
#define NH 64
#define NW 64
#define NTAP 9
#define SEXP (NC*NC*NTAP)
#define QP 66
#define QN (QP*QP)                  /* 4356 padded pixels */
#define TILE_M 128
#define TILE_N 192
#define KC 32
#define NCHUNK 8
#define NTHREADS 384
#define A_TAP_BYTES 8192            /* 128 rows x 32 ch fp16, fragment-major */
#define A_CHUNK_BYTES (NTAP*A_TAP_BYTES)   /* 73728 */
#define B_PITCH 64                  /* 64B data; conflict-free for uint4 loads */
#define B_ROWS 328                  /* 192 + 2*67 = 326, padded */
#define B_BYTES (B_ROWS*B_PITCH)    /* 20992 */
#define SMEM_TOTAL (2*A_CHUNK_BYTES + 2*B_BYTES)  /* 189440 */
#define QTILES 23                   /* 23*192 = 4416 >= 4356 */
#define NTILES (NB*2*QTILES)        /* 736 */
#define GRIDX 148                   /* persistent: 1 CTA per SM */
#define FOLD_BLOCKS (SEXP/256)      /* 2304 */
#define XPAD_BLOCKS (4*QP*NB)       /* 4224 */

__device__ float g_pooled[NB*NC];   // zero at module load; conv re-zeroes at end
__device__ float g_routing[NB*4];
// A fp16 fragment-major: [b][otile(2)][chunk(8)][t(9)][inner 4096]
__device__ __align__(1024) __half g_weff[(size_t)NB*NTAP*NC*NC];
// B fp16: [b][q][c_perm], perm within 32-group: pos32 = tig*8 + kk*4 + khi*2 + e
__device__ __align__(1024) __half g_xpad[(size_t)NB*QN*NC];

// ------------------------------------------------------------------ helpers
__device__ __forceinline__ uint32_t s2u(const void* p){
    uint32_t a;
    asm("{ .reg .u64 t; cvta.to.shared.u64 t, %1; cvt.u32.u64 %0, t; }" : "=r"(a) : "l"(p));
    return a;
}
__device__ __forceinline__ void cp16(uint32_t dst, const void* src, int szbytes){
    asm volatile("cp.async.cg.shared.global [%0], [%1], 16, %2;"
                 :: "r"(dst), "l"(src), "r"(szbytes) : "memory");
}
__device__ __forceinline__ void cp_commit(){
    asm volatile("cp.async.commit_group;" ::: "memory");
}
template<int N> __device__ __forceinline__ void cp_wait(){
    asm volatile("cp.async.wait_group %0;" :: "n"(N) : "memory");
}
__device__ __forceinline__ void mma16(float* d, const uint4 a, const uint32_t b0,
                                      const uint32_t b1){
    asm volatile("mma.sync.aligned.m16n8k16.row.col.f32.f16.f16.f32 "
        "{%0,%1,%2,%3}, {%4,%5,%6,%7}, {%8,%9}, {%0,%1,%2,%3};"
        : "+f"(d[0]), "+f"(d[1]), "+f"(d[2]), "+f"(d[3])
        : "r"(a.x), "r"(a.y), "r"(a.z), "r"(a.w), "r"(b0), "r"(b1));
}

// ------------------------------------------------------------------ prep
// Fused xpad + global-average-pool: reads x once. Pool accumulates into
// g_pooled via atomics (conv zeroes it at kernel end for the next replay).
__global__ void xpad_pool_kernel(const float* __restrict__ x) {
    __shared__ float s[64*65];
    int blk = blockIdx.x;
    int c0 = (blk & 3) * 64;
    int hp = (blk >> 2) % QP;
    int b  = blk / (4*QP);
    int h = hp - 1;
    bool hv = (h >= 0 && h < NH);
    if (hv) {
        const float* xp = x + ((size_t)(b*NC + c0))*(NH*NW) + (size_t)h*NW;
        for (int j = 0; j < 16; ++j) {
            int idx = j*256 + threadIdx.x;
            int i = idx >> 6, w = idx & 63;
            s[w*65 + i] = xp[(size_t)i*(NH*NW) + w];
        }
    }
    __syncthreads();
    // pooling contribution: one row (64 w) x 64 channels
    if (hv && threadIdx.x < 64) {
        int i = threadIdx.x;
        float sum = 0.f;
        #pragma unroll 8
        for (int w = 0; w < 64; ++w) sum += s[w*65 + i];
        atomicAdd(&g_pooled[b*NC + c0 + i], sum * (1.0f/(NH*NW)));
    }
    // xpad write
    __half* op = g_xpad + ((size_t)b*QN + (size_t)hp*QP)*NC + c0;
    for (int j = 0; j < 17; ++j) {
        int idx = j*256 + threadIdx.x;
        if (idx >= QP*64) break;
        int i = idx & 63, wp = idx >> 6;
        float v = 0.f;
        if (hv && wp >= 1 && wp <= 64) v = s[(wp-1)*65 + i];
        int c32 = i & 31;
        int kk = (c32 >> 4) & 1, khi = (c32 >> 3) & 1;
        int tg = (c32 >> 1) & 3, e = c32 & 1;
        int ipos = (i & ~31) | (tg*8 + kk*4 + khi*2 + e);
        op[(size_t)wp*NC + ipos] = __float2half_rn(v);
    }
}

__global__ void route_kernel(const float* __restrict__ wr, const float* __restrict__ br) {
    int t = threadIdx.x;
    if (t >= NB*4) return;
    int b = t >> 2, e = t & 3;
    float acc = br[e];
    const float* pw = wr + e*NC;
    const float* pp = g_pooled + b*NC;
    #pragma unroll 8
    for (int c = 0; c < NC; ++c) acc = fmaf(pp[c], pw[c], acc);
    g_routing[t] = 1.f/(1.f + __expf(-acc));
}

// Destination-coalesced fold into [otile][chunk][t][inner] layout.
__global__ void fold_kernel(const float* __restrict__ we) {
    int lin = blockIdx.x * 256 + threadIdx.x;   // 0 .. 589823
    int inner = lin & 4095;
    int rest  = lin >> 12;
    int t     = rest % 9;
    int oc    = rest / 9;
    int chunk = oc & 7;
    int otile = oc >> 3;
    int e    = inner & 1;
    int reg  = (inner >> 1) & 3;
    int lane = (inner >> 3) & 31;
    int mblk = (inner >> 8) & 7;
    int kk   = inner >> 11;
    int tig = lane & 3, g8 = lane >> 2;
    int khi = reg >> 1, ohi = reg & 1;
    int o = otile*128 + mblk*16 + ohi*8 + g8;
    int c = chunk*32 + kk*16 + khi*8 + tig*2 + e;

    size_t wi = ((size_t)o*NC + c)*NTAP + t;
    float w0 = we[wi], w1 = we[wi + (size_t)SEXP];
    float w2 = we[wi + 2*(size_t)SEXP], w3 = we[wi + 3*(size_t)SEXP];
    #pragma unroll
    for (int b = 0; b < NB; ++b) {
        const float* r = g_routing + b*4;
        g_weff[(size_t)b*(NTAP*NC*NC) + lin] =
            __float2half_rn(w0*r[0] + w1*r[1] + w2*r[2] + w3*r[3]);
    }
}

// ------------------------------------------------------------------ conv GEMM
// smem: [A buf0 72KB][A buf1 72KB][B buf0 20.5KB][B buf1 20.5KB]
__device__ __forceinline__ void decode_tile(int tau, int& b, int& otile, int& q0){
    b = tau / (2*QTILES);
    int r = tau - b*(2*QTILES);
    otile = r / QTILES;
    q0 = (r - otile*QTILES) * TILE_N;
}

__device__ __forceinline__ void load_chunk(uint32_t sb, int bufsel, int chunk,
                                           int b, int otile, int q0, int tid)
{
    const __half* aG = g_weff + (size_t)b*(NTAP*NC*NC)
                     + (size_t)otile*(8*NTAP*4096) + (size_t)chunk*(NTAP*4096);
    uint32_t aDst = sb + bufsel*A_CHUNK_BYTES;
    #pragma unroll
    for (int j = 0; j < 12; ++j) {
        int seg = tid + j*NTHREADS;
        cp16(aDst + seg*16, aG + (size_t)seg*8, 16);
    }
    const __half* bC = g_xpad + (size_t)b*QN*NC + chunk*KC;
    uint32_t bDst = sb + 2*A_CHUNK_BYTES + bufsel*B_BYTES;
    #pragma unroll
    for (int jj = 0; jj < 4; ++jj) {
        int seg = tid + jj*NTHREADS;
        if (seg < 326*4) {
            int row = seg >> 2, j = seg & 3;
            int q = q0 - 67 + row;
            bool v = ((unsigned)q < (unsigned)QN);
            const __half* src = bC + (size_t)(v ? q : 0)*NC + j*8;
            cp16(bDst + row*B_PITCH + j*16, src, v ? 16 : 0);
        }
    }
}

__global__ void __launch_bounds__(NTHREADS, 1)
conv_mma_kernel(const float* __restrict__ gamma, const float* __restrict__ beta,
                const float* __restrict__ mean,  const float* __restrict__ var,
                float* __restrict__ out)
{
    extern __shared__ __align__(128) char smem[];
    const uint32_t sb = s2u(smem);
    const int tid = threadIdx.x, wid = tid >> 5, lid = tid & 31;
    const int wmM = wid & 3;          // 4 warps over M
    const int wnN = wid >> 2;         // 3 warps over N
    const int g = lid >> 2, tig = lid & 3;

    int tau = blockIdx.x;
    int cb = 0, cot = 0, cq0 = 0;
    int nb = 0, not2 = 0, nq0 = 0;
    if (tau < NTILES) {
        decode_tile(tau, cb, cot, cq0);
        nb = cb; not2 = cot; nq0 = cq0;

        float acc[2][8][4];
        #pragma unroll
        for (int mi = 0; mi < 2; ++mi)
            #pragma unroll
            for (int ni = 0; ni < 8; ++ni)
                #pragma unroll
                for (int k = 0; k < 4; ++k) acc[mi][ni][k] = 0.f;

        // prologue: (tile0, chunk0) -> buffer 0
        load_chunk(sb, 0, 0, cb, cot, cq0, tid);
        cp_commit();
        int cnt = 0;
        uint4 Br[2][8];

        #pragma unroll 1
        while (tau < NTILES) {
            #pragma unroll 1
            for (int chunk = 0; chunk < NCHUNK; ++chunk) {
                __syncthreads();
                if (chunk + 1 < NCHUNK) {
                    load_chunk(sb, (cnt+1) & 1, chunk + 1, cb, cot, cq0, tid);
                } else if (tau + GRIDX < NTILES) {
                    decode_tile(tau + GRIDX, nb, not2, nq0);
                    load_chunk(sb, (cnt+1) & 1, 0, nb, not2, nq0, tid);
                }
                cp_commit();
                cp_wait<1>();
                __syncthreads();

                const char* aBuf = smem + (cnt & 1)*A_CHUNK_BYTES;
                const char* bBase = smem + 2*A_CHUNK_BYTES + (cnt & 1)*B_BYTES;
                const char* bLane = bBase + (wnN*64 + g + 67)*B_PITCH + tig*16;

                // preload tap 0 B fragments (shift -67)
                {
                    const char* bW = bLane + (-67)*B_PITCH;
                    #pragma unroll
                    for (int ni = 0; ni < 8; ++ni)
                        Br[0][ni] = *(const uint4*)(bW + ni*8*B_PITCH);
                }
                #pragma unroll
                for (int t = 0; t < NTAP; ++t) {
                    const char* aT = aBuf + t*A_TAP_BYTES;
                    if (t + 1 < NTAP) {
                        const int dh2 = (t+1) / 3, dw2 = (t+1) - dh2*3;
                        const char* bW = bLane + ((dh2-1)*QP + (dw2-1))*B_PITCH;
                        #pragma unroll
                        for (int ni = 0; ni < 8; ++ni)
                            Br[(t+1) & 1][ni] = *(const uint4*)(bW + ni*8*B_PITCH);
                    }
                    const uint4* cur = Br[t & 1];
                    #pragma unroll
                    for (int kk = 0; kk < 2; ++kk) {
                        uint4 a[2];
                        #pragma unroll
                        for (int mi = 0; mi < 2; ++mi)
                            a[mi] = *(const uint4*)(aT + ((kk*8 + wmM*2 + mi)*32 + lid)*16);
                        #pragma unroll
                        for (int mi = 0; mi < 2; ++mi)
                            #pragma unroll
                            for (int ni = 0; ni < 8; ++ni) {
                                uint32_t b0 = kk ? cur[ni].z : cur[ni].x;
                                uint32_t b1 = kk ? cur[ni].w : cur[ni].y;
                                mma16(acc[mi][ni], a[mi], b0, b1);
                            }
                    }
                }
                cnt++;
            }

            // ---------------- epilogue (next tile's chunk0 already in flight)
            {
                const int o0 = cot * TILE_M;
                float inv[2][2], add[2][2];
                #pragma unroll
                for (int mi = 0; mi < 2; ++mi)
                    #pragma unroll
                    for (int hi = 0; hi < 2; ++hi) {
                        int o = o0 + wmM*32 + mi*16 + g + hi*8;
                        float iv = gamma[o] * rsqrtf(var[o] + 1e-5f);
                        inv[mi][hi] = iv;
                        add[mi][hi] = beta[o] - mean[o] * iv;
                    }
                #pragma unroll
                for (int mi = 0; mi < 2; ++mi) {
                    #pragma unroll
                    for (int ni = 0; ni < 8; ++ni) {
                        #pragma unroll
                        for (int k = 0; k < 4; ++k) {
                            int hi = k >> 1, c = k & 1;
                            int q = cq0 + wnN*64 + ni*8 + 2*tig + c;
                            int hp = q / QP, wp = q - hp*QP;
                            if (q < QN && hp >= 1 && hp <= NH && wp >= 1 && wp <= NW) {
                                int o = o0 + wmM*32 + mi*16 + g + hi*8;
                                float z = acc[mi][ni][k] * inv[mi][hi] + add[mi][hi];
                                out[(((size_t)cb*NC + o)*NH + hp - 1)*NW + wp - 1] =
                                    z / (1.f + __expf(-z));
                            }
                            acc[mi][ni][k] = 0.f;
                        }
                    }
                }
            }
            tau += GRIDX;
            cb = nb; cot = not2; cq0 = nq0;
        }
    }

    // reset pooled accumulator for the next graph replay (after route used it)
    if (blockIdx.x == 0) {
        for (int i = tid; i < NB*NC; i += NTHREADS) g_pooled[i] = 0.f;
    }
}

// ------------------------------------------------------------------ launch
extern "C" void kernel_launch(void* const* d_in, const int* in_sizes, int n_in,
                              void* d_out, int out_size) {
    const float* x        = (const float*)d_in[0];
    const float* w_route  = (const float*)d_in[1];
    const float* b_route  = (const float*)d_in[2];
    const float* w_expert = (const float*)d_in[3];
    const float* bn_gamma = (const float*)d_in[4];
    const float* bn_beta  = (const float*)d_in[5];
    const float* bn_mean  = (const float*)d_in[6];
    const float* bn_var   = (const float*)d_in[7];
    float* out = (float*)d_out;

    cudaFuncSetAttribute(conv_mma_kernel,
                         cudaFuncAttributeMaxDynamicSharedMemorySize, SMEM_TOTAL);

    xpad_pool_kernel<<<XPAD_BLOCKS, 256>>>(x);
    route_kernel<<<1, 64>>>(w_route, b_route);
    fold_kernel<<<FOLD_BLOCKS, 256>>>(w_expert);
    conv_mma_kernel<<<GRIDX, NTHREADS, SMEM_TOTAL>>>(bn_gamma, bn_beta, bn_mean, bn_var, out);
}